// round 12
// baseline (speedup 1.0000x reference)
#include <cuda_runtime.h>
#include <cstdint>

#define S_LEN 4096
#define ROTN  32

// B fragments in per-lane load order, tf32-rounded (see scan_kernel).
__device__ uint4  g_Mfrag[2 * 2 * 8 * 32];
// Packed RoPE table: g_sc[spos*16 + 4p+tig] = {sin c0, sin c1, cos c0, cos c1}
__device__ float4 g_sc[S_LEN * 16];

__device__ __forceinline__ uint32_t f2tf32(float f) {
    uint32_t o;
    asm("cvt.rna.satfinite.tf32.f32 %0, %1;" : "=r"(o) : "f"(f));
    return o;
}
__device__ __forceinline__ uint32_t smem_u32(const void* p) {
    uint32_t a;
    asm("{ .reg .u64 t; cvta.to.shared.u64 t, %1; cvt.u32.u64 %0, t; }"
        : "=r"(a) : "l"(p));
    return a;
}

// Accurate fp32 sincos for x in [0, ~4100] (immune to --use_fast_math).
__device__ __forceinline__ float2 acc_sincos(float x) {
    float n = rintf(x * 0.636619772367581343f);
    float r = fmaf(n, -1.57079625129699707031e+00f, x);
    r = fmaf(n, -7.54978941586159635335e-08f, r);
    r = fmaf(n, -5.39030252995776476554e-15f, r);
    int q = (int)n & 3;
    float r2 = r * r;
    float ps = -1.9515296e-4f;
    ps = fmaf(ps, r2, 8.3321608e-3f);
    ps = fmaf(ps, r2, -1.6666654e-1f);
    float sr = fmaf(ps * r2, r, r);
    float pc = 2.4433157e-5f;
    pc = fmaf(pc, r2, -1.3887316e-3f);
    pc = fmaf(pc, r2, 4.1666646e-2f);
    pc = fmaf(pc, r2, -4.9999997e-1f);
    float cr = fmaf(pc, r2, 1.0f);
    float2 o;
    if (q == 0)      { o.x = sr;  o.y = cr;  }
    else if (q == 1) { o.x = cr;  o.y = -sr; }
    else if (q == 2) { o.x = -sr; o.y = -cr; }
    else             { o.x = -cr; o.y = sr;  }
    return o;
}

// ============================ scan kernel ==================================
__global__ void __launch_bounds__(256, 1)
scan_kernel(const float* __restrict__ thetas,
            const float* __restrict__ theta_scale,
            const float* __restrict__ rmat,
            const int*   __restrict__ pairs) {
    __shared__ float Ms[64][65];
    __shared__ float AB[ROTN][4];
    __shared__ int   PJ[ROTN][2];
    const int tid = threadIdx.x;

    float th_v = 0.f, ts_v = 0.f;
    int pi = 0, pj = 0;
    if (tid < ROTN) {
        th_v = thetas[tid];
        ts_v = theta_scale[0];
        pi = pairs[2 * tid];
        pj = pairs[2 * tid + 1];
    }

    #pragma unroll
    for (int it = 0; it < 16; ++it) {
        int idx = tid + 256 * it;
        int k = idx >> 6, c = idx & 63;
        int pc = (c < 32) ? (2 * c) : (2 * (c - 32) + 1);
        Ms[k][c] = rmat[k * 64 + pc];
    }

    if (tid < ROTN) {
        float th = th_v * ts_v;
        float c = cosf(th), s = sinf(th);
        AB[tid][0] = (1.0f + 2.0f * c - 2.0f * c * c) * (1.0f / 3.0f);
        AB[tid][1] = (2.0f * s - 2.0f * s * c) * (1.0f / 3.0f);
        AB[tid][2] = -(2.0f * s + 2.0f * c * s) * (1.0f / 3.0f);
        AB[tid][3] = (2.0f * c + 1.0f - 2.0f * s * s) * (1.0f / 3.0f);
        PJ[tid][0] = pi;
        PJ[tid][1] = pj;
    }
    __syncthreads();

    if (tid < 64) {
        #pragma unroll
        for (int s = ROTN - 1; s >= 0; --s) {
            int i = PJ[s][0], j = PJ[s][1];
            float a = AB[s][0], b = AB[s][1], gm = AB[s][2], d = AB[s][3];
            float mi = Ms[i][tid], mj = Ms[j][tid];
            Ms[i][tid] = a * mi + gm * mj;
            Ms[j][tid] = b * mi + d * mj;
        }
    }
    __syncthreads();

    #pragma unroll
    for (int it = 0; it < 4; ++it) {
        int idx = tid + 256 * it;
        int lane = idx & 31;
        int s    = (idx >> 5) & 7;
        int pp   = (idx >> 8) & 1;
        int pw   = (idx >> 9) & 1;
        int g = lane >> 2, tig = lane & 3;
        int p  = 2 * pw + pp;
        int nA = 8 * p + g, nB = nA + 32;
        int k0 = 8 * s + 2 * tig, k1 = k0 + 1;
        uint4 q;
        q.x = f2tf32(Ms[k0][nA]);
        q.y = f2tf32(Ms[k1][nA]);
        q.z = f2tf32(Ms[k0][nB]);
        q.w = f2tf32(Ms[k1][nB]);
        g_Mfrag[idx] = q;
    }
}

// ============================ table kernel =================================
__global__ void __launch_bounds__(256, 4)
table_kernel(const float* __restrict__ inv_freq) {
    int idx  = blockIdx.x * 256 + threadIdx.x;   // 65536 = S_LEN*16
    int spos = idx >> 4, j = idx & 15;
    float f0 = inv_freq[2 * j];
    float f1 = inv_freq[2 * j + 1];
    float2 sc0 = acc_sincos((float)spos * f0);
    float2 sc1 = acc_sincos((float)spos * f1);
    float4 r;
    r.x = sc0.x;
    r.y = sc1.x;
    r.z = sc0.y;
    r.w = sc1.y;
    g_sc[idx] = r;
}

// ============================ main kernel ==================================
// 64-row tile per CTA, 2 warps, grid 8192 -> ~8 CTAs/SM (reg-fit), 8 staggered
// tile pipelines per SM for smoother DRAM. Warp w owns n-pairs {2w, 2w+1} for
// ALL 4 m-tiles. LDS.64 A loads via k-permuted frags; B frags via LDG.128.
// Epilogue: RoPE -> shared sEp (both warps fill their column halves) ->
// __syncthreads -> coalesced STG.128 by all 64 threads.
#define XSTRIDE 72
#define ESTRIDE 76

__device__ __forceinline__ void mma16n8k8(float* c, const uint32_t* a,
                                          uint32_t b0, uint32_t b1) {
    asm volatile(
        "mma.sync.aligned.m16n8k8.row.col.f32.tf32.tf32.f32 "
        "{%0,%1,%2,%3}, {%4,%5,%6,%7}, {%8,%9}, {%0,%1,%2,%3};"
        : "+f"(c[0]), "+f"(c[1]), "+f"(c[2]), "+f"(c[3])
        : "r"(a[0]), "r"(a[1]), "r"(a[2]), "r"(a[3]), "r"(b0), "r"(b1));
}

__global__ void __launch_bounds__(64, 8)
cre_hmma_kernel(const float* __restrict__ x, float* __restrict__ out) {
    __shared__ uint32_t sX[64 * XSTRIDE];                  // 18432 B
    __shared__ __align__(16) float sEp[16 * ESTRIDE];      //  4864 B

    const int tid  = threadIdx.x;      // 0..63
    const int w    = tid >> 5;         // 0..1
    const int lane = tid & 31;
    const int g    = lane >> 2;
    const int tig  = lane & 3;
    const size_t rowBase = (size_t)blockIdx.x * 64;

    // ---- Stage x tile (64 rows) with cp.async ----
    {
        const float4* X4 = (const float4*)(x + rowBase * 64);
        const uint32_t sbase = smem_u32(sX);
        #pragma unroll
        for (int it = 0; it < 16; ++it) {
            int idx4 = tid + 64 * it;
            int r = idx4 >> 4, q = idx4 & 15;
            uint32_t dst = sbase + (uint32_t)(r * XSTRIDE + 4 * q) * 4u;
            asm volatile("cp.async.cg.shared.global [%0], [%1], 16;"
                         :: "r"(dst), "l"(X4 + idx4));
        }
        asm volatile("cp.async.commit_group;" ::: "memory");
    }

    // ---- B fragments for pairs {2w, 2w+1} ----
    uint32_t bA[2][8][2], bB[2][8][2];
    #pragma unroll
    for (int pp = 0; pp < 2; ++pp) {
        #pragma unroll
        for (int s = 0; s < 8; ++s) {
            uint4 q = g_Mfrag[(((w * 2 + pp) * 8) + s) * 32 + lane];
            bA[pp][s][0] = q.x;
            bA[pp][s][1] = q.y;
            bB[pp][s][0] = q.z;
            bB[pp][s][1] = q.w;
        }
    }
    asm volatile("cp.async.wait_group 0;" ::: "memory");
    __syncthreads();

    #pragma unroll
    for (int mt = 0; mt < 4; ++mt) {
        float cA[2][4] = {{0.f,0.f,0.f,0.f},{0.f,0.f,0.f,0.f}};
        float cB[2][4] = {{0.f,0.f,0.f,0.f},{0.f,0.f,0.f,0.f}};
        const uint32_t* xlow  = sX + (mt * 16 + g) * XSTRIDE + 2 * tig;
        const uint32_t* xhigh = xlow + 8 * XSTRIDE;

        #pragma unroll
        for (int s = 0; s < 8; ++s) {
            uint2 lo = *(const uint2*)(xlow  + 8 * s);
            uint2 hi = *(const uint2*)(xhigh + 8 * s);
            uint32_t a[4];
            a[0] = f2tf32(__uint_as_float(lo.x));
            a[1] = f2tf32(__uint_as_float(hi.x));
            a[2] = f2tf32(__uint_as_float(lo.y));
            a[3] = f2tf32(__uint_as_float(hi.y));
            #pragma unroll
            for (int pp = 0; pp < 2; ++pp) {
                mma16n8k8(cA[pp], a, bA[pp][s][0], bA[pp][s][1]);
                mma16n8k8(cB[pp], a, bB[pp][s][0], bB[pp][s][1]);
            }
        }

        // ---- RoPE + stage (warp w fills its column halves) ----
        const size_t R0 = rowBase + mt * 16;
        const int spos = (int)((R0 >> 4) & (S_LEN - 1));
        #pragma unroll
        for (int pp = 0; pp < 2; ++pp) {
            const int p  = 2 * w + pp;
            const int cf = 8 * p + 2 * tig;
            float4 sc = g_sc[spos * 16 + 4 * p + tig];
            float2 v;
            v.x = cA[pp][0] * sc.z - cB[pp][0] * sc.x;
            v.y = cA[pp][1] * sc.w - cB[pp][1] * sc.y;
            *(float2*)(sEp + g * ESTRIDE + cf) = v;
            v.x = cA[pp][0] * sc.x + cB[pp][0] * sc.z;
            v.y = cA[pp][1] * sc.y + cB[pp][1] * sc.w;
            *(float2*)(sEp + g * ESTRIDE + 32 + cf) = v;
            v.x = cA[pp][2] * sc.z - cB[pp][2] * sc.x;
            v.y = cA[pp][3] * sc.w - cB[pp][3] * sc.y;
            *(float2*)(sEp + (g + 8) * ESTRIDE + cf) = v;
            v.x = cA[pp][2] * sc.x + cB[pp][2] * sc.z;
            v.y = cA[pp][3] * sc.y + cB[pp][3] * sc.w;
            *(float2*)(sEp + (g + 8) * ESTRIDE + 32 + cf) = v;
        }

        __syncthreads();

        // ---- Coalesced store: 16 rows x 256 B by all 64 threads ----
        float4* o4 = (float4*)(out + R0 * 64);
        #pragma unroll
        for (int j = 0; j < 4; ++j) {
            int c = j * 64 + tid;            // 0..255
            int r = c >> 4, c16 = c & 15;
            float4 v = *(const float4*)(sEp + r * ESTRIDE + c16 * 4);
            o4[c] = v;
        }

        __syncthreads();
    }
}

// ---------------------------------------------------------------------------
extern "C" void kernel_launch(void* const* d_in, const int* in_sizes, int n_in,
                              void* d_out, int out_size) {
    const float* x      = (const float*)d_in[0];
    const float* thetas = (const float*)d_in[1];
    const float* tscale = (const float*)d_in[2];
    const float* rmat   = (const float*)d_in[3];
    const float* invf   = (const float*)d_in[4];
    const int*   pairs  = (const int*)d_in[5];
    float*       out    = (float*)d_out;

    scan_kernel<<<1, 256>>>(thetas, tscale, rmat, pairs);
    table_kernel<<<256, 256>>>(invf);

    int rows   = in_sizes[0] / 64;     // 524288
    int blocks = rows / 64;            // 8192
    cre_hmma_kernel<<<blocks, 64>>>(x, out);
}